// round 13
// baseline (speedup 1.0000x reference)
#include <cuda_runtime.h>

#define NS 64
#define NB 8192
#define HP 128
#define HH 64
#define NR 11
#define RC 231
#define GAPN 10
#define MCN 10000
#define DT (1.0f/64.0f)
#define NHB 50

typedef unsigned long long u64;

__device__ int   g_histp[NHB*NR*20];
__device__ __align__(16) float g_A[NS*RC*HH];
__device__ __align__(16) float g_B[NS*RC];
__device__ __align__(16) float g_W3[NS*NR*6*HH];
__device__ __align__(16) float g_b3[NS*NR*6];
__device__ float4 g_P1[NS*6*32];
__device__ float4 g_P2[NS*HH*32];
__device__ float4 g_Pb[NS*32];
__device__ float4 g_Pb2[NS*32];

__global__ void __launch_bounds__(256) kh(const float* __restrict__ mc,
                                          const float* __restrict__ jm){
  __shared__ int sh[NR*20];
  int tid=threadIdx.x;
  if(tid<NR*20) sh[tid]=0;
  __syncthreads();
  const int chunk=(MCN*NR+NHB-1)/NHB;
  int lo=blockIdx.x*chunk, hi=min(lo+chunk,MCN*NR);
  for(int i=lo+tid;i<hi;i+=256){
    int r=i%NR; float u=mc[i]; const float* row=jm+r*20; int c=0;
    #pragma unroll
    for(int j=0;j<20;j++) c += (u<row[j]) ? 1 : 0;
    atomicAdd(&sh[r*20+(20-c)],1);
  }
  __syncthreads();
  if(tid<NR*20) g_histp[blockIdx.x*NR*20+tid]=sh[tid];
}

__global__ void __launch_bounds__(256) kA2B(const float* __restrict__ Wf3,
                                            const float* __restrict__ bf3,
                                            const float* __restrict__ jl,
                                            const float* __restrict__ jr,
                                            const float* __restrict__ cr){
  int t=blockIdx.x, chunk=blockIdx.y;
  __shared__ float sW[HP*65];
  __shared__ float swt[4][HP];
  __shared__ float sb[HP];
  __shared__ float s_jl[20*HP];
  __shared__ float s_jr[NR*HP];
  __shared__ float s_mc[NR*HP];
  __shared__ int   s_hist[NR*20];
  __shared__ float s_cr[NR];
  int tid=threadIdx.x;
  for(int idx=tid; idx<HH*HP; idx+=256){
    int h=idx>>7, p=idx&127;
    sW[p*65+h]=Wf3[t*HH*HP+idx];
  }
  if(tid<HP) sb[tid]=bf3[t*HP+tid];
  for(int i=tid;i<20*HP;i+=256) s_jl[i]=jl[i];
  for(int i=tid;i<NR*HP;i+=256) s_jr[i]=jr[i];
  if(tid<NR) s_cr[tid]=cr[tid];
  if(tid<NR*20){
    int a=0;
    #pragma unroll 10
    for(int b=0;b<NHB;b++) a+=g_histp[b*NR*20+tid];
    s_hist[tid]=a;
  }
  __syncthreads();
  for(int i=tid;i<NR*HP;i+=256){
    int r=i>>7, p=i&127;
    float acc=0.f;
    #pragma unroll
    for(int k=0;k<GAPN;k++){
      acc += (float)s_hist[r*20+k]      * s_jl[k*HP+p];
      acc += (float)s_hist[r*20+10+k]   * s_jl[(GAPN+k)*HP+p];
    }
    s_mc[i]=s_cr[r]*(acc*(1.0f/MCN));
  }
  __syncthreads();
  int h=tid&63, g=tid>>6;
  int rcEnd=min(chunk*29+29,RC);
  for(int rc0=chunk*29; rc0<rcEnd; rc0+=4){
    __syncthreads();
    for(int idx=tid; idx<4*HP; idx+=256){
      int gg=idx>>7, p=idx&127; int rc=rc0+gg;
      float w=0.f;
      if(rc<RC){
        int r=rc/21, c=rc-r*21, d=c-10;
        float j=0.f;
        if(d>0) j=s_jl[(d-1)*HP+p]; else if(d<0) j=s_jl[(GAPN+(-d-1))*HP+p];
        w=s_jr[r*HP+p]*(j - s_mc[r*HP+p]*DT);
      }
      swt[gg][p]=w;
    }
    __syncthreads();
    int rc=rc0+g;
    if(rc<rcEnd){
      float a=0.f;
      #pragma unroll 8
      for(int p=0;p<HP;p++) a += sW[p*65+h]*swt[g][p];
      g_A[(t*RC+rc)*HH+h]=a;
    }
    if(tid<4 && rc0+tid<rcEnd){
      float b0=0.f,b1=0.f;
      #pragma unroll 8
      for(int p=0;p<HP;p+=2){ b0+=sb[p]*swt[tid][p]; b1+=sb[p+1]*swt[tid][p+1]; }
      g_B[t*RC+rc0+tid]=b0+b1;
    }
  }
}

__global__ void __launch_bounds__(384) kEP(const float* __restrict__ W3,
                                           const float* __restrict__ emb,
                                           const float* __restrict__ b3,
  const float* __restrict__ W1, const float* __restrict__ b1,
  const float* __restrict__ W2, const float* __restrict__ b2,
  const float* __restrict__ Wf1, const float* __restrict__ bf1,
  const float* __restrict__ Wf2, const float* __restrict__ bf2){
  int t=blockIdx.x, tid=threadIdx.x;
  __shared__ float se[NR*HP];
  for(int i=tid;i<NR*HP;i+=384) se[i]=emb[t*NR*HP+i];
  __syncthreads();
  int h=tid/6, o=tid-h*6;
  float acc[NR];
  #pragma unroll
  for(int r=0;r<NR;r++) acc[r]=0.f;
  const float* W=W3+t*HH*768+h*768+o;
  for(int p=0;p<HP;p++){
    float wv=W[p*6];
    #pragma unroll
    for(int r=0;r<NR;r++) acc[r] += se[r*HP+p]*wv;
  }
  #pragma unroll
  for(int r=0;r<NR;r++) g_W3[((t*NR+r)*6+o)*HH+h]=acc[r];
  if(tid<6){
    float a2[NR];
    #pragma unroll
    for(int r=0;r<NR;r++) a2[r]=0.f;
    const float* bb=b3+t*768+tid;
    for(int p=0;p<HP;p++){
      float bv=bb[p*6];
      #pragma unroll
      for(int r=0;r<NR;r++) a2[r] += se[r*HP+p]*bv;
    }
    #pragma unroll
    for(int r=0;r<NR;r++) g_b3[(t*NR+r)*6+tid]=a2[r];
  }
  for(int idx=tid; idx<HH*32; idx+=384){
    int i=idx>>5, l=idx&31; int b=t*HH*HH+i*HH+2*l;
    g_P2[(t*HH+i)*32+l]=make_float4(W2[b],W2[b+1],Wf2[b],Wf2[b+1]);
  }
  for(int idx=tid; idx<6*32; idx+=384){
    int i=idx>>5, l=idx&31; int b=t*6*HH+i*HH+2*l;
    g_P1[(t*6+i)*32+l]=make_float4(W1[b],W1[b+1],Wf1[b],Wf1[b+1]);
  }
  if(tid<32){
    int b=t*HH+2*tid;
    g_Pb [t*32+tid]=make_float4(b1[b],b1[b+1],bf1[b],bf1[b+1]);
    g_Pb2[t*32+tid]=make_float4(b2[b],b2[b+1],bf2[b],bf2[b+1]);
  }
}

__device__ __forceinline__ float tanh_(float x){
  float e=__expf(2.f*x); return 1.f-__fdividef(2.f,e+1.f);
}

// ---- packed f32x2 helpers (two exact fp32 ops per instruction) ----
__device__ __forceinline__ u64 pk2(float lo, float hi){
  u64 r;
  asm("mov.b64 %0,{%1,%2};" : "=l"(r)
      : "r"(__float_as_uint(lo)), "r"(__float_as_uint(hi)));
  return r;
}
__device__ __forceinline__ void upk2(u64 v, float& lo, float& hi){
  unsigned a,b;
  asm("mov.b64 {%0,%1},%2;" : "=r"(a), "=r"(b) : "l"(v));
  lo=__uint_as_float(a); hi=__uint_as_float(b);
}
__device__ __forceinline__ void fma2(u64& d, u64 a, u64 b){
  asm("fma.rn.f32x2 %0,%1,%2,%0;" : "+l"(d) : "l"(a), "l"(b));
}

struct PS {
  int rt; int act;
  float xi[3], yi[3];
  float up, fun;
};

__device__ __forceinline__ bool refl2(float* p, float* m){
  float nr=sqrtf(p[0]*p[0]+p[1]*p[1]+p[2]*p[2]);
  if(nr>5.0f){
    float d=fmaxf(nr,1e-12f);
    float n0=p[0]/d, n1=p[1]/d, n2=p[2]/d;
    float s=10.0f-nr;
    p[0]=n0*s; p[1]=n1*s; p[2]=n2*s;
    float q0=n0*m[0]+n1*m[3]+n2*m[6];
    float q1=n0*m[1]+n1*m[4]+n2*m[7];
    float q2=n0*m[2]+n1*m[5]+n2*m[8];
    m[0]-=2.f*n0*q0; m[1]-=2.f*n0*q1; m[2]-=2.f*n0*q2;
    m[3]-=2.f*n1*q0; m[4]-=2.f*n1*q1; m[5]-=2.f*n1*q2;
    m[6]-=2.f*n2*q0; m[7]-=2.f*n2*q1; m[8]-=2.f*n2*q2;
    return true;
  }
  return false;
}

__device__ __forceinline__ void pre_step(const PS& s, const float* s_jm,
    const float* s_cr, float jv, float sv, int& drt, int& ridx){
  ridx = min(max(s.rt-10,0),10);
  drt = 0;
  if(jv < s_cr[ridx]*DT){
    const float* row=s_jm+ridx*20; int c=0;
    #pragma unroll
    for(int j=0;j<20;j++) c += (sv<row[j]) ? 1 : 0;
    int ind=20-c;
    drt = (ind<10) ? (ind+1) : (-(ind-9));
  }
}

__device__ __forceinline__ bool post_step(PS& s,
    float* sxt, float* sgx, float* sgy, bool writer,
    const float* gu, float jump, float db0, float db1,
    float dy0, float dy1, float dy2,
    int drt, int ridx, const float* s_cfr, const float* s_inv){
  float xt0=sxt[0], xt1=sxt[1], xt2=sxt[2];
  float gx[9], gy[9];
  #pragma unroll
  for(int k=0;k<9;k++){ gx[k]=sgx[k]; gy[k]=sgy[k]; }

  float dot=xt0*xt0+xt1*xt1+xt2*xt2;
  float aa=fminf(fmaxf(xt2*rsqrtf(fmaxf(dot,1e-24f)),-1.f),1.f);
  float st=-aa, ct=sqrtf(fmaxf(1.f-aa*aa,0.f));
  float dxy=xt0*xt0+xt1*xt1;
  float cp,sp;
  if(dxy>0.f){
    float inv=rsqrtf(dxy);
    cp=xt0*inv; sp=xt1*inv;
  } else { cp=1.f; sp=0.f; }
  float T[9]={cp*ct,-sp,cp*st, sp*ct,cp,sp*st, -st,0.f,ct};

  float v0=gu[0]*gx[0]+gu[1]*gx[3]+gu[2]*gx[6];
  float v1=gu[0]*gx[1]+gu[1]*gx[4]+gu[2]*gx[7];
  float v2=gu[0]*gx[2]+gu[1]*gx[5]+gu[2]*gx[8];
  float w1=v0*T[1]+v1*T[4]+v2*T[7];
  float w2=v0*T[2]+v1*T[5]+v2*T[8];
  float gux0=-w2, gux1=w1;
  float q0=gu[3]*gy[0]+gu[4]*gy[3]+gu[5]*gy[6];
  float q1=gu[3]*gy[1]+gu[4]*gy[4]+gu[5]*gy[7];
  float q2=gu[3]*gy[2]+gu[4]*gy[5]+gu[5]*gy[8];
  float sdx=s_inv[s.rt-10];
  float diff=sdx*(gux0*db0+gux1*db1)+(q0*dy0+q1*dy1+q2*dy2)+jump;
  s.up += __expf(-s.fun)*diff;
  s.fun += s_cfr[ridx]*DT;
  float dX0=sdx*db0, dX1=sdx*db1;
  float x2=dX0*dX0;
  float s_t = 1.f - x2*(0.5f - x2*(0.0416666667f - x2*0.00138888889f));
  float c_t = -dX0*(1.f - x2*(0.166666667f - x2*(0.00833333333f - x2*1.98412698e-4f)));
  float y2=dX1*dX1;
  float c_p = 1.f - y2*(0.5f - y2*(0.0416666667f - y2*0.00138888889f));
  float s_p = dX1*(1.f - y2*(0.166666667f - y2*(0.00833333333f - y2*1.98412698e-4f)));
  float cx=s_t*c_p-1.f, cy=s_t*s_p, cz=c_t;
  float d0=T[0]*cx+T[1]*cy+T[2]*cz;
  float d1=T[3]*cx+T[4]*cy+T[5]*cz;
  float d2=T[6]*cx+T[7]*cy+T[8]*cz;
  xt0+=d0; xt1+=d1; xt2+=d2;
  s.xi[0]+=gx[0]*d0+gx[1]*d1+gx[2]*d2;
  s.xi[1]+=gx[3]*d0+gx[4]*d1+gx[5]*d2;
  s.xi[2]+=gx[6]*d0+gx[7]*d1+gx[8]*d2;
  s.yi[0]+=gy[0]*dy0+gy[1]*dy1+gy[2]*dy2;
  s.yi[1]+=gy[3]*dy0+gy[4]*dy1+gy[5]*dy2;
  s.yi[2]+=gy[6]*dy0+gy[7]*dy1+gy[8]*dy2;
  s.rt=min(max(s.rt+drt,10),20);
  bool wx=refl2(s.xi,gx);
  bool wy=refl2(s.yi,gy);
  if(writer){
    sxt[0]=xt0; sxt[1]=xt1; sxt[2]=xt2;
    if(wx){
      #pragma unroll
      for(int k=0;k<9;k++) sgx[k]=gx[k];
    }
    if(wy){
      #pragma unroll
      for(int k=0;k<9;k++) sgy[k]=gy[k];
    }
  }
  float e0=s.xi[0]-s.yi[0], e1=s.xi[1]-s.yi[1], e2=s.xi[2]-s.yi[2];
  return sqrtf(e0*e0+e1*e1+e2*e2)<0.1f;
}

__global__ void __launch_bounds__(128,5) kmain(
  const float* __restrict__ u, const float* __restrict__ jm,
  const float* __restrict__ cr, const float* __restrict__ cfr,
  const int* __restrict__ rt0, const float* __restrict__ xt0,
  const float* __restrict__ yt0, const float* __restrict__ dBx,
  const float* __restrict__ dBy, const float* __restrict__ juf,
  const float* __restrict__ suf, float* __restrict__ out)
{
  int tid=threadIdx.x, l=tid&31, wl=tid>>5;
  int wp=blockIdx.x*4+wl;
  int pA=2*wp, pB=2*wp+1;
  // hidden vectors stored pre-duplicated: s_Xg[i] = (hg_i, hg_i), s_Xf[i] = (hf_i, hf_i)
  __shared__ __align__(16) float2 s_Ag[4][HH], s_Af[4][HH];
  __shared__ __align__(16) float2 s_Bg[4][HH], s_Bf[4][HH];
  __shared__ float s_gx[4][2][9], s_gy[4][2][9], s_xt[4][2][3];
  __shared__ float s_jm[NR*20];
  __shared__ float s_cr[NR], s_cfr[NR], s_inv[NR];
  for(int i=tid;i<NR*20;i+=128) s_jm[i]=jm[i];
  if(tid<NR){
    s_cr[tid]=cr[tid]; s_cfr[tid]=cfr[tid];
    s_inv[tid]=1.0f/(float)(tid+10);
  }
  __syncthreads();

  PS A, B;
  A.rt=rt0[pA]; B.rt=rt0[pB];
  #pragma unroll
  for(int k=0;k<3;k++){
    A.xi[k]=xt0[pA*3+k]; A.yi[k]=yt0[pA*3+k];
    B.xi[k]=xt0[pB*3+k]; B.yi[k]=yt0[pB*3+k];
  }
  float u0=u[0];
  A.up=u0; B.up=u0; A.fun=0.f; B.fun=0.f; A.act=1; B.act=1;
  bool writer=(l==0);
  if(writer){
    #pragma unroll
    for(int k=0;k<3;k++){ s_xt[wl][0][k]=A.xi[k]; s_xt[wl][1][k]=B.xi[k]; }
    #pragma unroll
    for(int k=0;k<9;k++){
      float id=(k==0||k==4||k==8)?1.f:0.f;
      s_gx[wl][0][k]=id; s_gy[wl][0][k]=id;
      s_gx[wl][1][k]=id; s_gy[wl][1][k]=id;
    }
  }
  __syncwarp();

  for(int t=0;t<NS;t++){
    float2 ju2=*(const float2*)(juf + t*NB + pA);
    float2 su2=*(const float2*)(suf + t*NB + pA);
    float4 dbx4=*(const float4*)(dBx + (size_t)(t*NB+pA)*2);
    const float* dyp = dBy + (size_t)(t*NB+pA)*3;
    float2 dya=*(const float2*)(dyp);
    float2 dym=*(const float2*)(dyp+2);
    float2 dyb=*(const float2*)(dyp+4);
    float dyA0=dya.x, dyA1=dya.y, dyA2=dym.x;
    float dyB0=dym.y, dyB1=dyb.x, dyB2=dyb.y;

    int drtA,ridxA,drtB,ridxB;
    pre_step(A,s_jm,s_cr,ju2.x,su2.x,drtA,ridxA);
    pre_step(B,s_jm,s_cr,ju2.y,su2.y,drtB,ridxB);

    // ---- layer 1 (both MLPs, both particles) ----
    float4 bb=g_Pb[t*32+l];
    float4 a1A=bb, a1B=bb;
    {
      const float4* Wp=g_P1+t*6*32;
      #pragma unroll
      for(int i=0;i<3;i++){
        float4 wv=Wp[i*32+l];
        a1A.x+=A.xi[i]*wv.x; a1A.y+=A.xi[i]*wv.y;
        a1A.z+=A.xi[i]*wv.z; a1A.w+=A.xi[i]*wv.w;
        a1B.x+=B.xi[i]*wv.x; a1B.y+=B.xi[i]*wv.y;
        a1B.z+=B.xi[i]*wv.z; a1B.w+=B.xi[i]*wv.w;
      }
      #pragma unroll
      for(int i=0;i<3;i++){
        float4 wv=Wp[(3+i)*32+l];
        a1A.x+=A.yi[i]*wv.x; a1A.y+=A.yi[i]*wv.y;
        a1A.z+=A.yi[i]*wv.z; a1A.w+=A.yi[i]*wv.w;
        a1B.x+=B.yi[i]*wv.x; a1B.y+=B.yi[i]*wv.y;
        a1B.z+=B.yi[i]*wv.z; a1B.w+=B.yi[i]*wv.w;
      }
    }
    // store duplicated hidden values: lane l owns h[2l], h[2l+1]
    {
      float tgx=tanh_(a1A.x), tgy=tanh_(a1A.y);
      float tfx=tanh_(a1A.z), tfy=tanh_(a1A.w);
      ((float4*)&s_Ag[wl][2*l])[0]=make_float4(tgx,tgx,tgy,tgy);
      ((float4*)&s_Af[wl][2*l])[0]=make_float4(tfx,tfx,tfy,tfy);
      tgx=tanh_(a1B.x); tgy=tanh_(a1B.y);
      tfx=tanh_(a1B.z); tfy=tanh_(a1B.w);
      ((float4*)&s_Bg[wl][2*l])[0]=make_float4(tgx,tgx,tgy,tgy);
      ((float4*)&s_Bf[wl][2*l])[0]=make_float4(tfx,tfx,tfy,tfy);
    }
    __syncwarp();
    // ---- layer 2: packed f32x2 FMAs ----
    float4 b2v=g_Pb2[t*32+l];
    u64 accAg=pk2(b2v.x,b2v.y), accAf=pk2(b2v.z,b2v.w);
    u64 accBg=accAg, accBf=accAf;
    {
      const ulonglong2* WpU=(const ulonglong2*)(g_P2+t*HH*32);
      #pragma unroll 8
      for(int i=0;i<HH;i+=2){
        ulonglong2 ag=*(const ulonglong2*)&s_Ag[wl][i];
        ulonglong2 af=*(const ulonglong2*)&s_Af[wl][i];
        ulonglong2 bg=*(const ulonglong2*)&s_Bg[wl][i];
        ulonglong2 bf=*(const ulonglong2*)&s_Bf[wl][i];
        ulonglong2 w0=WpU[i*32+l];
        ulonglong2 w1=WpU[(i+1)*32+l];
        fma2(accAg,ag.x,w0.x); fma2(accAf,af.x,w0.y);
        fma2(accBg,bg.x,w0.x); fma2(accBf,bf.x,w0.y);
        fma2(accAg,ag.y,w1.x); fma2(accAf,af.y,w1.y);
        fma2(accBg,bg.y,w1.x); fma2(accBf,bf.y,w1.y);
      }
    }
    __syncwarp();
    float a2Ax,a2Ay,a2Az,a2Aw,a2Bx,a2By,a2Bz,a2Bw;
    upk2(accAg,a2Ax,a2Ay); upk2(accAf,a2Az,a2Aw);
    upk2(accBg,a2Bx,a2By); upk2(accBf,a2Bz,a2Bw);
    float2 h2A=make_float2(tanh_(a2Ax),tanh_(a2Ay));
    float2 f2A=make_float2(tanh_(a2Az),tanh_(a2Aw));
    float2 h2B=make_float2(tanh_(a2Bx),tanh_(a2By));
    float2 f2B=make_float2(tanh_(a2Bz),tanh_(a2Bw));
    // ---- layer 3 partials + batched butterfly ----
    int cA=drtA+10, cB=drtB+10;
    float v[14];
    {
      const float* WpA=g_W3+(t*NR+ridxA)*6*HH;
      const float* WpB=g_W3+(t*NR+ridxB)*6*HH;
      #pragma unroll
      for(int o=0;o<6;o++){
        float2 wa=*(const float2*)(WpA+o*HH+2*l);
        float2 wb=*(const float2*)(WpB+o*HH+2*l);
        v[o]  =h2A.x*wa.x+h2A.y*wa.y;
        v[7+o]=h2B.x*wb.x+h2B.y*wb.y;
      }
      float2 aa2=*(const float2*)(g_A+(t*RC+ridxA*21+cA)*HH+2*l);
      float2 ab2=*(const float2*)(g_A+(t*RC+ridxB*21+cB)*HH+2*l);
      v[6] =f2A.x*aa2.x+f2A.y*aa2.y;
      v[13]=f2B.x*ab2.x+f2B.y*ab2.y;
    }
    #pragma unroll
    for(int k=16;k;k>>=1){
      #pragma unroll
      for(int j=0;j<14;j++) v[j]+=__shfl_xor_sync(0xffffffffu,v[j],k);
    }
    float guA[6], guB[6];
    {
      const float* bpA=g_b3+(t*NR+ridxA)*6;
      const float* bpB=g_b3+(t*NR+ridxB)*6;
      #pragma unroll
      for(int o=0;o<6;o++){ guA[o]=v[o]+bpA[o]; guB[o]=v[7+o]+bpB[o]; }
    }
    float jumpA=v[6]+g_B[t*RC+ridxA*21+cA];
    float jumpB=v[13]+g_B[t*RC+ridxB*21+cB];

    if(A.act){
      if(post_step(A,&s_xt[wl][0][0],&s_gx[wl][0][0],&s_gy[wl][0][0],writer,
                   guA,jumpA,dbx4.x,dbx4.y,dyA0,dyA1,dyA2,drtA,ridxA,s_cfr,s_inv)) A.act=0;
    }
    if(B.act){
      if(post_step(B,&s_xt[wl][1][0],&s_gx[wl][1][0],&s_gy[wl][1][0],writer,
                   guB,jumpB,dbx4.z,dbx4.w,dyB0,dyB1,dyB2,drtB,ridxB,s_cfr,s_inv)) B.act=0;
    }
    __syncwarp();
    if(!A.act && !B.act) break;
  }
  if(l==0){
    float e0=A.xi[0]-A.yi[0], e1=A.xi[1]-A.yi[1], e2=A.xi[2]-A.yi[2];
    out[pA]=A.up;
    out[NB+pA]=A.act ? __expf(-(e0*e0+e1*e1+e2*e2))*__expf(-A.fun) : 0.f;
    e0=B.xi[0]-B.yi[0]; e1=B.xi[1]-B.yi[1]; e2=B.xi[2]-B.yi[2];
    out[pB]=B.up;
    out[NB+pB]=B.act ? __expf(-(e0*e0+e1*e1+e2*e2))*__expf(-B.fun) : 0.f;
  }
}

extern "C" void kernel_launch(void* const* d_in, const int* in_sizes, int n_in,
                              void* d_out, int out_size) {
  const float* u   =(const float*)d_in[0];
  const float* jr  =(const float*)d_in[1];
  const float* jl  =(const float*)d_in[2];
  const float* W1  =(const float*)d_in[3];
  const float* b1  =(const float*)d_in[4];
  const float* W2  =(const float*)d_in[5];
  const float* b2  =(const float*)d_in[6];
  const float* W3  =(const float*)d_in[7];
  const float* b3  =(const float*)d_in[8];
  const float* emb =(const float*)d_in[9];
  const float* Wf1 =(const float*)d_in[10];
  const float* bf1 =(const float*)d_in[11];
  const float* Wf2 =(const float*)d_in[12];
  const float* bf2 =(const float*)d_in[13];
  const float* Wf3 =(const float*)d_in[14];
  const float* bf3 =(const float*)d_in[15];
  const int*   rt0 =(const int*)  d_in[16];
  const float* xt0 =(const float*)d_in[17];
  const float* yt0 =(const float*)d_in[18];
  const float* dBx =(const float*)d_in[19];
  const float* dBy =(const float*)d_in[20];
  const float* juf =(const float*)d_in[21];
  const float* suf =(const float*)d_in[22];
  const float* mcu =(const float*)d_in[23];
  const float* jm  =(const float*)d_in[24];
  const float* cr  =(const float*)d_in[25];
  const float* cfr =(const float*)d_in[26];

  kh<<<NHB,256>>>(mcu,jm);
  kA2B<<<dim3(NS,8),256>>>(Wf3,bf3,jl,jr,cr);
  kEP<<<NS,384>>>(W3,emb,b3,W1,b1,W2,b2,Wf1,bf1,Wf2,bf2);
  kmain<<<NB/8,128>>>(u,jm,cr,cfr,rt0,xt0,yt0,dBx,dBy,juf,suf,(float*)d_out);
}

// round 14
// speedup vs baseline: 1.7878x; 1.7878x over previous
#include <cuda_runtime.h>

#define NS 64
#define NB 8192
#define HP 128
#define HH 64
#define NR 11
#define RC 231
#define GAPN 10
#define MCN 10000
#define DT (1.0f/64.0f)
#define NHB 50

__device__ int   g_histp[NHB*NR*20];
__device__ __align__(16) float g_A[NS*RC*HH];
__device__ __align__(16) float g_B[NS*RC];
__device__ __align__(16) float g_W3[NS*NR*6*HH];
__device__ __align__(16) float g_b3[NS*NR*6];
__device__ float4 g_P1[NS*6*32];
__device__ float4 g_P2[NS*HH*32];
__device__ float4 g_Pb[NS*32];
__device__ float4 g_Pb2[NS*32];
// phase-1 -> phase-2 buffers
__device__ __align__(16) float g_in6[NS*6*NB];
__device__ __align__(16) float g_a6[NS*6*NB];
__device__ __align__(16) float g_c0[NS*NB];
__device__ __align__(16) float g_wt[NS*NB];
__device__ __align__(16) int   g_idx[NS*NB];
__device__ __align__(16) float g_d[NS*NB];

__global__ void __launch_bounds__(256) kh(const float* __restrict__ mc,
                                          const float* __restrict__ jm){
  __shared__ int sh[NR*20];
  int tid=threadIdx.x;
  if(tid<NR*20) sh[tid]=0;
  __syncthreads();
  const int chunk=(MCN*NR+NHB-1)/NHB;
  int lo=blockIdx.x*chunk, hi=min(lo+chunk,MCN*NR);
  for(int i=lo+tid;i<hi;i+=256){
    int r=i%NR; float u=mc[i]; const float* row=jm+r*20; int c=0;
    #pragma unroll
    for(int j=0;j<20;j++) c += (u<row[j]) ? 1 : 0;
    atomicAdd(&sh[r*20+(20-c)],1);
  }
  __syncthreads();
  if(tid<NR*20) g_histp[blockIdx.x*NR*20+tid]=sh[tid];
}

__global__ void __launch_bounds__(256) kA2B(const float* __restrict__ Wf3,
                                            const float* __restrict__ bf3,
                                            const float* __restrict__ jl,
                                            const float* __restrict__ jr,
                                            const float* __restrict__ cr){
  int t=blockIdx.x, chunk=blockIdx.y;
  __shared__ float sW[HP*65];
  __shared__ float swt[4][HP];
  __shared__ float sb[HP];
  __shared__ float s_jl[20*HP];
  __shared__ float s_jr[NR*HP];
  __shared__ float s_mc[NR*HP];
  __shared__ int   s_hist[NR*20];
  __shared__ float s_cr[NR];
  int tid=threadIdx.x;
  for(int idx=tid; idx<HH*HP; idx+=256){
    int h=idx>>7, p=idx&127;
    sW[p*65+h]=Wf3[t*HH*HP+idx];
  }
  if(tid<HP) sb[tid]=bf3[t*HP+tid];
  for(int i=tid;i<20*HP;i+=256) s_jl[i]=jl[i];
  for(int i=tid;i<NR*HP;i+=256) s_jr[i]=jr[i];
  if(tid<NR) s_cr[tid]=cr[tid];
  if(tid<NR*20){
    int a=0;
    #pragma unroll 10
    for(int b=0;b<NHB;b++) a+=g_histp[b*NR*20+tid];
    s_hist[tid]=a;
  }
  __syncthreads();
  for(int i=tid;i<NR*HP;i+=256){
    int r=i>>7, p=i&127;
    float acc=0.f;
    #pragma unroll
    for(int k=0;k<GAPN;k++){
      acc += (float)s_hist[r*20+k]      * s_jl[k*HP+p];
      acc += (float)s_hist[r*20+10+k]   * s_jl[(GAPN+k)*HP+p];
    }
    s_mc[i]=s_cr[r]*(acc*(1.0f/MCN));
  }
  __syncthreads();
  int h=tid&63, g=tid>>6;
  int rcEnd=min(chunk*29+29,RC);
  for(int rc0=chunk*29; rc0<rcEnd; rc0+=4){
    __syncthreads();
    for(int idx=tid; idx<4*HP; idx+=256){
      int gg=idx>>7, p=idx&127; int rc=rc0+gg;
      float w=0.f;
      if(rc<RC){
        int r=rc/21, c=rc-r*21, d=c-10;
        float j=0.f;
        if(d>0) j=s_jl[(d-1)*HP+p]; else if(d<0) j=s_jl[(GAPN+(-d-1))*HP+p];
        w=s_jr[r*HP+p]*(j - s_mc[r*HP+p]*DT);
      }
      swt[gg][p]=w;
    }
    __syncthreads();
    int rc=rc0+g;
    if(rc<rcEnd){
      float a=0.f;
      #pragma unroll 8
      for(int p=0;p<HP;p++) a += sW[p*65+h]*swt[g][p];
      g_A[(t*RC+rc)*HH+h]=a;
    }
    if(tid<4 && rc0+tid<rcEnd){
      float b0=0.f,b1=0.f;
      #pragma unroll 8
      for(int p=0;p<HP;p+=2){ b0+=sb[p]*swt[tid][p]; b1+=sb[p+1]*swt[tid][p+1]; }
      g_B[t*RC+rc0+tid]=b0+b1;
    }
  }
}

__global__ void __launch_bounds__(384) kEP(const float* __restrict__ W3,
                                           const float* __restrict__ emb,
                                           const float* __restrict__ b3,
  const float* __restrict__ W1, const float* __restrict__ b1,
  const float* __restrict__ W2, const float* __restrict__ b2,
  const float* __restrict__ Wf1, const float* __restrict__ bf1,
  const float* __restrict__ Wf2, const float* __restrict__ bf2){
  int t=blockIdx.x, tid=threadIdx.x;
  __shared__ float se[NR*HP];
  for(int i=tid;i<NR*HP;i+=384) se[i]=emb[t*NR*HP+i];
  __syncthreads();
  int h=tid/6, o=tid-h*6;
  float acc[NR];
  #pragma unroll
  for(int r=0;r<NR;r++) acc[r]=0.f;
  const float* W=W3+t*HH*768+h*768+o;
  for(int p=0;p<HP;p++){
    float wv=W[p*6];
    #pragma unroll
    for(int r=0;r<NR;r++) acc[r] += se[r*HP+p]*wv;
  }
  #pragma unroll
  for(int r=0;r<NR;r++) g_W3[((t*NR+r)*6+o)*HH+h]=acc[r];
  if(tid<6){
    float a2[NR];
    #pragma unroll
    for(int r=0;r<NR;r++) a2[r]=0.f;
    const float* bb=b3+t*768+tid;
    for(int p=0;p<HP;p++){
      float bv=bb[p*6];
      #pragma unroll
      for(int r=0;r<NR;r++) a2[r] += se[r*HP+p]*bv;
    }
    #pragma unroll
    for(int r=0;r<NR;r++) g_b3[(t*NR+r)*6+tid]=a2[r];
  }
  for(int idx=tid; idx<HH*32; idx+=384){
    int i=idx>>5, l=idx&31; int b=t*HH*HH+i*HH+2*l;
    g_P2[(t*HH+i)*32+l]=make_float4(W2[b],W2[b+1],Wf2[b],Wf2[b+1]);
  }
  for(int idx=tid; idx<6*32; idx+=384){
    int i=idx>>5, l=idx&31; int b=t*6*HH+i*HH+2*l;
    g_P1[(t*6+i)*32+l]=make_float4(W1[b],W1[b+1],Wf1[b],Wf1[b+1]);
  }
  if(tid<32){
    int b=t*HH+2*tid;
    g_Pb [t*32+tid]=make_float4(b1[b],b1[b+1],bf1[b],bf1[b+1]);
    g_Pb2[t*32+tid]=make_float4(b2[b],b2[b+1],bf2[b],bf2[b+1]);
  }
}

__device__ __forceinline__ float tanh_(float x){
  float e=__expf(2.f*x); return 1.f-__fdividef(2.f,e+1.f);
}

__device__ __forceinline__ void refl(float* p, float* m){
  float nr=sqrtf(p[0]*p[0]+p[1]*p[1]+p[2]*p[2]);
  if(nr>5.0f){
    float d=fmaxf(nr,1e-12f);
    float n0=p[0]/d, n1=p[1]/d, n2=p[2]/d;
    float s=10.0f-nr;
    p[0]=n0*s; p[1]=n1*s; p[2]=n2*s;
    float q0=n0*m[0]+n1*m[3]+n2*m[6];
    float q1=n0*m[1]+n1*m[4]+n2*m[7];
    float q2=n0*m[2]+n1*m[5]+n2*m[8];
    m[0]-=2.f*n0*q0; m[1]-=2.f*n0*q1; m[2]-=2.f*n0*q2;
    m[3]-=2.f*n1*q0; m[4]-=2.f*n1*q1; m[5]-=2.f*n1*q2;
    m[6]-=2.f*n2*q0; m[7]-=2.f*n2*q1; m[8]-=2.f*n2*q2;
  }
}

// ---- Phase 1: trajectory (thread-per-particle, network-independent) ----
__global__ void __launch_bounds__(256) ktraj(
  const int* __restrict__ rt0, const float* __restrict__ xt0,
  const float* __restrict__ yt0, const float* __restrict__ dBx,
  const float* __restrict__ dBy, const float* __restrict__ juf,
  const float* __restrict__ suf, const float* __restrict__ jm,
  const float* __restrict__ cr, const float* __restrict__ cfr,
  float* __restrict__ out)
{
  int tid=threadIdx.x;
  __shared__ float s_jm[NR*20];
  __shared__ float s_cr[NR], s_cfr[NR], s_inv[NR];
  if(tid<NR*20) s_jm[tid]=jm[tid];
  if(tid<NR){
    s_cr[tid]=cr[tid]; s_cfr[tid]=cfr[tid];
    s_inv[tid]=1.0f/(float)(tid+10);
  }
  __syncthreads();
  int p=blockIdx.x*256+tid;

  int rt=rt0[p];
  float xt[3], xi[3], yi[3], gx[9], gy[9];
  #pragma unroll
  for(int k=0;k<3;k++){
    xt[k]=xt0[p*3+k]; xi[k]=xt[k]; yi[k]=yt0[p*3+k];
  }
  #pragma unroll
  for(int k=0;k<9;k++){
    float id=(k==0||k==4||k==8)?1.f:0.f;
    gx[k]=id; gy[k]=id;
  }
  float fun=0.f; int act=1;

  for(int t=0;t<NS;t++){
    // store MLP inputs (state BEFORE this step's update)
    #pragma unroll
    for(int k=0;k<3;k++){
      g_in6[(t*6+k)*NB+p]=xi[k];
      g_in6[(t*6+3+k)*NB+p]=yi[k];
    }
    float jv=juf[t*NB+p], sv=suf[t*NB+p];
    float2 db=*(const float2*)(dBx+(size_t)(t*NB+p)*2);
    const float* dyp=dBy+(size_t)(t*NB+p)*3;
    float dy0=dyp[0], dy1=dyp[1], dy2=dyp[2];

    int ridx=min(max(rt-10,0),10);
    int drt=0;
    if(jv<s_cr[ridx]*DT){
      const float* row=s_jm+ridx*20; int c=0;
      #pragma unroll
      for(int j=0;j<20;j++) c += (sv<row[j]) ? 1 : 0;
      int ind=20-c;
      drt=(ind<10)?(ind+1):(-(ind-9));
    }
    // T from xt
    float dot=xt[0]*xt[0]+xt[1]*xt[1]+xt[2]*xt[2];
    float aa=fminf(fmaxf(xt[2]*rsqrtf(fmaxf(dot,1e-24f)),-1.f),1.f);
    float st=-aa, ct=sqrtf(fmaxf(1.f-aa*aa,0.f));
    float dxy=xt[0]*xt[0]+xt[1]*xt[1];
    float cp,sp;
    if(dxy>0.f){
      float inv=rsqrtf(dxy);
      cp=xt[0]*inv; sp=xt[1]*inv;
    } else { cp=1.f; sp=0.f; }
    float T[9]={cp*ct,-sp,cp*st, sp*ct,cp,sp*st, -st,0.f,ct};
    float sdx=s_inv[rt-10];
    // linear functionals: diff = a6 . gu + jump-part
    float m0=sdx*(db.y*T[1]-db.x*T[2]);
    float m1=sdx*(db.y*T[4]-db.x*T[5]);
    float m2=sdx*(db.y*T[7]-db.x*T[8]);
    float a0=gx[0]*m0+gx[1]*m1+gx[2]*m2;
    float a1=gx[3]*m0+gx[4]*m1+gx[5]*m2;
    float a2=gx[6]*m0+gx[7]*m1+gx[8]*m2;
    float a3=gy[0]*dy0+gy[1]*dy1+gy[2]*dy2;
    float a4=gy[3]*dy0+gy[4]*dy1+gy[5]*dy2;
    float a5=gy[6]*dy0+gy[7]*dy1+gy[8]*dy2;
    int c=drt+10, rc=ridx*21+c;
    const float* bp=g_b3+(t*NR+ridx)*6;
    float c0=a0*bp[0]+a1*bp[1]+a2*bp[2]+a3*bp[3]+a4*bp[4]+a5*bp[5]+g_B[t*RC+rc];
    g_a6[(t*6+0)*NB+p]=a0; g_a6[(t*6+1)*NB+p]=a1; g_a6[(t*6+2)*NB+p]=a2;
    g_a6[(t*6+3)*NB+p]=a3; g_a6[(t*6+4)*NB+p]=a4; g_a6[(t*6+5)*NB+p]=a5;
    g_c0[t*NB+p]=c0;
    g_wt[t*NB+p]=act ? __expf(-fun) : 0.f;
    g_idx[t*NB+p]=(ridx<<8)|c;

    if(act){
      fun += s_cfr[ridx]*DT;
      float dX0=sdx*db.x, dX1=sdx*db.y;
      float x2=dX0*dX0;
      float s_t = 1.f - x2*(0.5f - x2*(0.0416666667f - x2*0.00138888889f));
      float c_t = -dX0*(1.f - x2*(0.166666667f - x2*(0.00833333333f - x2*1.98412698e-4f)));
      float y2=dX1*dX1;
      float c_p = 1.f - y2*(0.5f - y2*(0.0416666667f - y2*0.00138888889f));
      float s_p = dX1*(1.f - y2*(0.166666667f - y2*(0.00833333333f - y2*1.98412698e-4f)));
      float cx=s_t*c_p-1.f, cy=s_t*s_p, cz=c_t;
      float d0=T[0]*cx+T[1]*cy+T[2]*cz;
      float d1=T[3]*cx+T[4]*cy+T[5]*cz;
      float d2=T[6]*cx+T[7]*cy+T[8]*cz;
      xt[0]+=d0; xt[1]+=d1; xt[2]+=d2;
      xi[0]+=gx[0]*d0+gx[1]*d1+gx[2]*d2;
      xi[1]+=gx[3]*d0+gx[4]*d1+gx[5]*d2;
      xi[2]+=gx[6]*d0+gx[7]*d1+gx[8]*d2;
      yi[0]+=a3; yi[1]+=a4; yi[2]+=a5;
      rt=min(max(rt+drt,10),20);
      refl(xi,gx); refl(yi,gy);
      float e0=xi[0]-yi[0], e1=xi[1]-yi[1], e2=xi[2]-yi[2];
      if(sqrtf(e0*e0+e1*e1+e2*e2)<0.1f) act=0;
    }
  }
  float e0=xi[0]-yi[0], e1=xi[1]-yi[1], e2=xi[2]-yi[2];
  out[NB+p]=act ? __expf(-(e0*e0+e1*e1+e2*e2))*__expf(-fun) : 0.f;
}

// ---- Phase 2: 524288 independent MLP rows, 2 rows/warp ----
__global__ void __launch_bounds__(128) kmlp(){
  int tid=threadIdx.x, l=tid&31, wl=tid>>5;
  __shared__ __align__(16) float2 shA[4][HH];
  __shared__ __align__(16) float2 shB[4][HH];
  int gw=blockIdx.x*4+wl;
  int row=2*gw;
  int t=row>>13, p=row&(NB-1);

  float in6A[6], in6B[6], a6A[6], a6B[6];
  #pragma unroll
  for(int k=0;k<6;k++){
    in6A[k]=g_in6[(t*6+k)*NB+p];
    in6B[k]=g_in6[(t*6+k)*NB+p+1];
    a6A[k]=g_a6[(t*6+k)*NB+p];
    a6B[k]=g_a6[(t*6+k)*NB+p+1];
  }
  int idxA=g_idx[t*NB+p], idxB=g_idx[t*NB+p+1];

  // layer 1
  float4 bb=g_Pb[t*32+l];
  float4 a1A=bb, a1B=bb;
  {
    const float4* Wp=g_P1+t*6*32;
    #pragma unroll
    for(int i=0;i<6;i++){
      float4 wv=Wp[i*32+l];
      a1A.x+=in6A[i]*wv.x; a1A.y+=in6A[i]*wv.y;
      a1A.z+=in6A[i]*wv.z; a1A.w+=in6A[i]*wv.w;
      a1B.x+=in6B[i]*wv.x; a1B.y+=in6B[i]*wv.y;
      a1B.z+=in6B[i]*wv.z; a1B.w+=in6B[i]*wv.w;
    }
  }
  ((float4*)shA[wl])[l]=make_float4(tanh_(a1A.x),tanh_(a1A.z),tanh_(a1A.y),tanh_(a1A.w));
  ((float4*)shB[wl])[l]=make_float4(tanh_(a1B.x),tanh_(a1B.z),tanh_(a1B.y),tanh_(a1B.w));
  __syncwarp();
  // layer 2
  float4 b2v=g_Pb2[t*32+l];
  float4 a2A=b2v, a2B=b2v;
  {
    const float4* Wp=g_P2+t*HH*32;
    #pragma unroll 8
    for(int i=0;i<HH;i++){
      float2 xA=shA[wl][i];
      float2 xB=shB[wl][i];
      float4 wv=Wp[i*32+l];
      a2A.x+=xA.x*wv.x; a2A.y+=xA.x*wv.y;
      a2A.z+=xA.y*wv.z; a2A.w+=xA.y*wv.w;
      a2B.x+=xB.x*wv.x; a2B.y+=xB.x*wv.y;
      a2B.z+=xB.y*wv.z; a2B.w+=xB.y*wv.w;
    }
  }
  float2 h2A=make_float2(tanh_(a2A.x),tanh_(a2A.y));
  float2 f2A=make_float2(tanh_(a2A.z),tanh_(a2A.w));
  float2 h2B=make_float2(tanh_(a2B.x),tanh_(a2B.y));
  float2 f2B=make_float2(tanh_(a2B.z),tanh_(a2B.w));
  // layer 3: fold a6 before reduction -> single scalar per row
  int ridxA=idxA>>8, rcA=ridxA*21+(idxA&255);
  int ridxB=idxB>>8, rcB=ridxB*21+(idxB&255);
  float sA=0.f, sB=0.f;
  {
    const float* WpA=g_W3+(t*NR+ridxA)*6*HH;
    const float* WpB=g_W3+(t*NR+ridxB)*6*HH;
    #pragma unroll
    for(int o=0;o<6;o++){
      float2 wa=*(const float2*)(WpA+o*HH+2*l);
      float2 wb=*(const float2*)(WpB+o*HH+2*l);
      sA += a6A[o]*(h2A.x*wa.x+h2A.y*wa.y);
      sB += a6B[o]*(h2B.x*wb.x+h2B.y*wb.y);
    }
    float2 aa2=*(const float2*)(g_A+(t*RC+rcA)*HH+2*l);
    float2 ab2=*(const float2*)(g_A+(t*RC+rcB)*HH+2*l);
    sA += f2A.x*aa2.x+f2A.y*aa2.y;
    sB += f2B.x*ab2.x+f2B.y*ab2.y;
  }
  #pragma unroll
  for(int k=16;k;k>>=1){
    sA+=__shfl_xor_sync(0xffffffffu,sA,k);
    sB+=__shfl_xor_sync(0xffffffffu,sB,k);
  }
  if(l==0){
    g_d[t*NB+p]  =g_wt[t*NB+p]  *(sA+g_c0[t*NB+p]);
    g_d[t*NB+p+1]=g_wt[t*NB+p+1]*(sB+g_c0[t*NB+p+1]);
  }
}

// ---- Phase 3: sequential t-order accumulation of u_pre ----
__global__ void __launch_bounds__(256) kfin(const float* __restrict__ u,
                                            float* __restrict__ out){
  int p=blockIdx.x*256+threadIdx.x;
  float acc=u[0];
  #pragma unroll 8
  for(int t=0;t<NS;t++) acc+=g_d[t*NB+p];
  out[p]=acc;
}

extern "C" void kernel_launch(void* const* d_in, const int* in_sizes, int n_in,
                              void* d_out, int out_size) {
  const float* u   =(const float*)d_in[0];
  const float* jr  =(const float*)d_in[1];
  const float* jl  =(const float*)d_in[2];
  const float* W1  =(const float*)d_in[3];
  const float* b1  =(const float*)d_in[4];
  const float* W2  =(const float*)d_in[5];
  const float* b2  =(const float*)d_in[6];
  const float* W3  =(const float*)d_in[7];
  const float* b3  =(const float*)d_in[8];
  const float* emb =(const float*)d_in[9];
  const float* Wf1 =(const float*)d_in[10];
  const float* bf1 =(const float*)d_in[11];
  const float* Wf2 =(const float*)d_in[12];
  const float* bf2 =(const float*)d_in[13];
  const float* Wf3 =(const float*)d_in[14];
  const float* bf3 =(const float*)d_in[15];
  const int*   rt0 =(const int*)  d_in[16];
  const float* xt0 =(const float*)d_in[17];
  const float* yt0 =(const float*)d_in[18];
  const float* dBx =(const float*)d_in[19];
  const float* dBy =(const float*)d_in[20];
  const float* juf =(const float*)d_in[21];
  const float* suf =(const float*)d_in[22];
  const float* mcu =(const float*)d_in[23];
  const float* jm  =(const float*)d_in[24];
  const float* cr  =(const float*)d_in[25];
  const float* cfr =(const float*)d_in[26];

  kh<<<NHB,256>>>(mcu,jm);
  kA2B<<<dim3(NS,8),256>>>(Wf3,bf3,jl,jr,cr);
  kEP<<<NS,384>>>(W3,emb,b3,W1,b1,W2,b2,Wf1,bf1,Wf2,bf2);
  ktraj<<<NB/256,256>>>(rt0,xt0,yt0,dBx,dBy,juf,suf,jm,cr,cfr,(float*)d_out);
  kmlp<<<NS*NB/8,128>>>();
  kfin<<<NB/256,256>>>(u,(float*)d_out);
}

// round 15
// speedup vs baseline: 2.1181x; 1.1848x over previous
#include <cuda_runtime.h>

#define NS 64
#define NB 8192
#define HP 128
#define HH 64
#define NR 11
#define RC 231
#define GAPN 10
#define MCN 10000
#define DT (1.0f/64.0f)
#define NHB 50

__device__ int   g_histp[NHB*NR*20];
__device__ __align__(16) float g_A[NS*RC*HH];
__device__ __align__(16) float g_B[NS*RC];
__device__ __align__(16) float g_W3[NS*NR*6*HH];
__device__ __align__(16) float g_b3[NS*NR*6];
__device__ float4 g_P1[NS*6*32];
__device__ float4 g_P2[NS*HH*32];
__device__ float4 g_Pb[NS*32];
__device__ float4 g_Pb2[NS*32];
__device__ __align__(16) float g_in6[NS*6*NB];
__device__ __align__(16) float g_a6[NS*6*NB];
__device__ __align__(16) float g_c0[NS*NB];
__device__ __align__(16) float g_wt[NS*NB];
__device__ __align__(16) int   g_idx[NS*NB];
__device__ __align__(16) float g_d[NS*NB];

__global__ void __launch_bounds__(256) kh(const float* __restrict__ mc,
                                          const float* __restrict__ jm){
  __shared__ int sh[NR*20];
  int tid=threadIdx.x;
  if(tid<NR*20) sh[tid]=0;
  __syncthreads();
  const int chunk=(MCN*NR+NHB-1)/NHB;
  int lo=blockIdx.x*chunk, hi=min(lo+chunk,MCN*NR);
  for(int i=lo+tid;i<hi;i+=256){
    int r=i%NR; float u=mc[i]; const float* row=jm+r*20; int c=0;
    #pragma unroll
    for(int j=0;j<20;j++) c += (u<row[j]) ? 1 : 0;
    atomicAdd(&sh[r*20+(20-c)],1);
  }
  __syncthreads();
  if(tid<NR*20) g_histp[blockIdx.x*NR*20+tid]=sh[tid];
}

__global__ void __launch_bounds__(256) kA2B(const float* __restrict__ Wf3,
                                            const float* __restrict__ bf3,
                                            const float* __restrict__ jl,
                                            const float* __restrict__ jr,
                                            const float* __restrict__ cr){
  int t=blockIdx.x, chunk=blockIdx.y;
  __shared__ float sW[HP*65];
  __shared__ float swt[4][HP];
  __shared__ float sb[HP];
  __shared__ float s_jl[20*HP];
  __shared__ float s_jr[NR*HP];
  __shared__ float s_mc[NR*HP];
  __shared__ int   s_hist[NR*20];
  __shared__ float s_cr[NR];
  int tid=threadIdx.x;
  for(int idx=tid; idx<HH*HP; idx+=256){
    int h=idx>>7, p=idx&127;
    sW[p*65+h]=Wf3[t*HH*HP+idx];
  }
  if(tid<HP) sb[tid]=bf3[t*HP+tid];
  for(int i=tid;i<20*HP;i+=256) s_jl[i]=jl[i];
  for(int i=tid;i<NR*HP;i+=256) s_jr[i]=jr[i];
  if(tid<NR) s_cr[tid]=cr[tid];
  if(tid<NR*20){
    int a=0;
    #pragma unroll 10
    for(int b=0;b<NHB;b++) a+=g_histp[b*NR*20+tid];
    s_hist[tid]=a;
  }
  __syncthreads();
  for(int i=tid;i<NR*HP;i+=256){
    int r=i>>7, p=i&127;
    float acc=0.f;
    #pragma unroll
    for(int k=0;k<GAPN;k++){
      acc += (float)s_hist[r*20+k]      * s_jl[k*HP+p];
      acc += (float)s_hist[r*20+10+k]   * s_jl[(GAPN+k)*HP+p];
    }
    s_mc[i]=s_cr[r]*(acc*(1.0f/MCN));
  }
  __syncthreads();
  int h=tid&63, g=tid>>6;
  int rcEnd=min(chunk*29+29,RC);
  for(int rc0=chunk*29; rc0<rcEnd; rc0+=4){
    __syncthreads();
    for(int idx=tid; idx<4*HP; idx+=256){
      int gg=idx>>7, p=idx&127; int rc=rc0+gg;
      float w=0.f;
      if(rc<RC){
        int r=rc/21, c=rc-r*21, d=c-10;
        float j=0.f;
        if(d>0) j=s_jl[(d-1)*HP+p]; else if(d<0) j=s_jl[(GAPN+(-d-1))*HP+p];
        w=s_jr[r*HP+p]*(j - s_mc[r*HP+p]*DT);
      }
      swt[gg][p]=w;
    }
    __syncthreads();
    int rc=rc0+g;
    if(rc<rcEnd){
      float a=0.f;
      #pragma unroll 8
      for(int p=0;p<HP;p++) a += sW[p*65+h]*swt[g][p];
      g_A[(t*RC+rc)*HH+h]=a;
    }
    if(tid<4 && rc0+tid<rcEnd){
      float b0=0.f,b1=0.f;
      #pragma unroll 8
      for(int p=0;p<HP;p+=2){ b0+=sb[p]*swt[tid][p]; b1+=sb[p+1]*swt[tid][p+1]; }
      g_B[t*RC+rc0+tid]=b0+b1;
    }
  }
}

__global__ void __launch_bounds__(384) kEP(const float* __restrict__ W3,
                                           const float* __restrict__ emb,
                                           const float* __restrict__ b3,
  const float* __restrict__ W1, const float* __restrict__ b1,
  const float* __restrict__ W2, const float* __restrict__ b2,
  const float* __restrict__ Wf1, const float* __restrict__ bf1,
  const float* __restrict__ Wf2, const float* __restrict__ bf2){
  int t=blockIdx.x, tid=threadIdx.x;
  __shared__ float se[NR*HP];
  for(int i=tid;i<NR*HP;i+=384) se[i]=emb[t*NR*HP+i];
  __syncthreads();
  int h=tid/6, o=tid-h*6;
  float acc[NR];
  #pragma unroll
  for(int r=0;r<NR;r++) acc[r]=0.f;
  const float* W=W3+t*HH*768+h*768+o;
  for(int p=0;p<HP;p++){
    float wv=W[p*6];
    #pragma unroll
    for(int r=0;r<NR;r++) acc[r] += se[r*HP+p]*wv;
  }
  #pragma unroll
  for(int r=0;r<NR;r++) g_W3[((t*NR+r)*6+o)*HH+h]=acc[r];
  if(tid<6){
    float a2[NR];
    #pragma unroll
    for(int r=0;r<NR;r++) a2[r]=0.f;
    const float* bb=b3+t*768+tid;
    for(int p=0;p<HP;p++){
      float bv=bb[p*6];
      #pragma unroll
      for(int r=0;r<NR;r++) a2[r] += se[r*HP+p]*bv;
    }
    #pragma unroll
    for(int r=0;r<NR;r++) g_b3[(t*NR+r)*6+tid]=a2[r];
  }
  for(int idx=tid; idx<HH*32; idx+=384){
    int i=idx>>5, l=idx&31; int b=t*HH*HH+i*HH+2*l;
    g_P2[(t*HH+i)*32+l]=make_float4(W2[b],W2[b+1],Wf2[b],Wf2[b+1]);
  }
  for(int idx=tid; idx<6*32; idx+=384){
    int i=idx>>5, l=idx&31; int b=t*6*HH+i*HH+2*l;
    g_P1[(t*6+i)*32+l]=make_float4(W1[b],W1[b+1],Wf1[b],Wf1[b+1]);
  }
  if(tid<32){
    int b=t*HH+2*tid;
    g_Pb [t*32+tid]=make_float4(b1[b],b1[b+1],bf1[b],bf1[b+1]);
    g_Pb2[t*32+tid]=make_float4(b2[b],b2[b+1],bf2[b],bf2[b+1]);
  }
}

__device__ __forceinline__ float tanh_(float x){
  float e=__expf(2.f*x); return 1.f-__fdividef(2.f,e+1.f);
}

__device__ __forceinline__ void refl(float* p, float* m){
  float nr=sqrtf(p[0]*p[0]+p[1]*p[1]+p[2]*p[2]);
  if(nr>5.0f){
    float d=fmaxf(nr,1e-12f);
    float n0=p[0]/d, n1=p[1]/d, n2=p[2]/d;
    float s=10.0f-nr;
    p[0]=n0*s; p[1]=n1*s; p[2]=n2*s;
    float q0=n0*m[0]+n1*m[3]+n2*m[6];
    float q1=n0*m[1]+n1*m[4]+n2*m[7];
    float q2=n0*m[2]+n1*m[5]+n2*m[8];
    m[0]-=2.f*n0*q0; m[1]-=2.f*n0*q1; m[2]-=2.f*n0*q2;
    m[3]-=2.f*n1*q0; m[4]-=2.f*n1*q1; m[5]-=2.f*n1*q2;
    m[6]-=2.f*n2*q0; m[7]-=2.f*n2*q1; m[8]-=2.f*n2*q2;
  }
}

// ---- Phase 1: trajectory; 64-thread blocks to spread across 128 SMs ----
__global__ void __launch_bounds__(64) ktraj(
  const int* __restrict__ rt0, const float* __restrict__ xt0,
  const float* __restrict__ yt0, const float* __restrict__ dBx,
  const float* __restrict__ dBy, const float* __restrict__ juf,
  const float* __restrict__ suf, const float* __restrict__ jm,
  const float* __restrict__ cr, const float* __restrict__ cfr,
  float* __restrict__ out)
{
  int tid=threadIdx.x;
  __shared__ float s_jm[NR*20];
  __shared__ float s_cr[NR], s_cfr[NR], s_inv[NR];
  for(int i=tid;i<NR*20;i+=64) s_jm[i]=jm[i];
  if(tid<NR){
    s_cr[tid]=cr[tid]; s_cfr[tid]=cfr[tid];
    s_inv[tid]=1.0f/(float)(tid+10);
  }
  __syncthreads();
  int p=blockIdx.x*64+tid;

  int rt=rt0[p];
  float xt[3], xi[3], yi[3], gx[9], gy[9];
  #pragma unroll
  for(int k=0;k<3;k++){
    xt[k]=xt0[p*3+k]; xi[k]=xt[k]; yi[k]=yt0[p*3+k];
  }
  #pragma unroll
  for(int k=0;k<9;k++){
    float id=(k==0||k==4||k==8)?1.f:0.f;
    gx[k]=id; gy[k]=id;
  }
  float fun=0.f; int act=1;

  for(int t=0;t<NS;t++){
    #pragma unroll
    for(int k=0;k<3;k++){
      g_in6[(t*6+k)*NB+p]=xi[k];
      g_in6[(t*6+3+k)*NB+p]=yi[k];
    }
    float jv=juf[t*NB+p], sv=suf[t*NB+p];
    float2 db=*(const float2*)(dBx+(size_t)(t*NB+p)*2);
    const float* dyp=dBy+(size_t)(t*NB+p)*3;
    float dy0=dyp[0], dy1=dyp[1], dy2=dyp[2];

    int ridx=min(max(rt-10,0),10);
    int drt=0;
    if(jv<s_cr[ridx]*DT){
      const float* row=s_jm+ridx*20; int c=0;
      #pragma unroll
      for(int j=0;j<20;j++) c += (sv<row[j]) ? 1 : 0;
      int ind=20-c;
      drt=(ind<10)?(ind+1):(-(ind-9));
    }
    float dot=xt[0]*xt[0]+xt[1]*xt[1]+xt[2]*xt[2];
    float aa=fminf(fmaxf(xt[2]*rsqrtf(fmaxf(dot,1e-24f)),-1.f),1.f);
    float st=-aa, ct=sqrtf(fmaxf(1.f-aa*aa,0.f));
    float dxy=xt[0]*xt[0]+xt[1]*xt[1];
    float cp,sp;
    if(dxy>0.f){
      float inv=rsqrtf(dxy);
      cp=xt[0]*inv; sp=xt[1]*inv;
    } else { cp=1.f; sp=0.f; }
    float T[9]={cp*ct,-sp,cp*st, sp*ct,cp,sp*st, -st,0.f,ct};
    float sdx=s_inv[rt-10];
    float m0=sdx*(db.y*T[1]-db.x*T[2]);
    float m1=sdx*(db.y*T[4]-db.x*T[5]);
    float m2=sdx*(db.y*T[7]-db.x*T[8]);
    float a0=gx[0]*m0+gx[1]*m1+gx[2]*m2;
    float a1=gx[3]*m0+gx[4]*m1+gx[5]*m2;
    float a2=gx[6]*m0+gx[7]*m1+gx[8]*m2;
    float a3=gy[0]*dy0+gy[1]*dy1+gy[2]*dy2;
    float a4=gy[3]*dy0+gy[4]*dy1+gy[5]*dy2;
    float a5=gy[6]*dy0+gy[7]*dy1+gy[8]*dy2;
    int c=drt+10, rc=ridx*21+c;
    const float* bp=g_b3+(t*NR+ridx)*6;
    float c0=a0*bp[0]+a1*bp[1]+a2*bp[2]+a3*bp[3]+a4*bp[4]+a5*bp[5]+g_B[t*RC+rc];
    g_a6[(t*6+0)*NB+p]=a0; g_a6[(t*6+1)*NB+p]=a1; g_a6[(t*6+2)*NB+p]=a2;
    g_a6[(t*6+3)*NB+p]=a3; g_a6[(t*6+4)*NB+p]=a4; g_a6[(t*6+5)*NB+p]=a5;
    g_c0[t*NB+p]=c0;
    g_wt[t*NB+p]=act ? __expf(-fun) : 0.f;
    g_idx[t*NB+p]=(ridx<<8)|c;

    if(act){
      fun += s_cfr[ridx]*DT;
      float dX0=sdx*db.x, dX1=sdx*db.y;
      float x2=dX0*dX0;
      float s_t = 1.f - x2*(0.5f - x2*(0.0416666667f - x2*0.00138888889f));
      float c_t = -dX0*(1.f - x2*(0.166666667f - x2*(0.00833333333f - x2*1.98412698e-4f)));
      float y2=dX1*dX1;
      float c_p = 1.f - y2*(0.5f - y2*(0.0416666667f - y2*0.00138888889f));
      float s_p = dX1*(1.f - y2*(0.166666667f - y2*(0.00833333333f - y2*1.98412698e-4f)));
      float cx=s_t*c_p-1.f, cy=s_t*s_p, cz=c_t;
      float d0=T[0]*cx+T[1]*cy+T[2]*cz;
      float d1=T[3]*cx+T[4]*cy+T[5]*cz;
      float d2=T[6]*cx+T[7]*cy+T[8]*cz;
      xt[0]+=d0; xt[1]+=d1; xt[2]+=d2;
      xi[0]+=gx[0]*d0+gx[1]*d1+gx[2]*d2;
      xi[1]+=gx[3]*d0+gx[4]*d1+gx[5]*d2;
      xi[2]+=gx[6]*d0+gx[7]*d1+gx[8]*d2;
      yi[0]+=a3; yi[1]+=a4; yi[2]+=a5;
      rt=min(max(rt+drt,10),20);
      refl(xi,gx); refl(yi,gy);
      float e0=xi[0]-yi[0], e1=xi[1]-yi[1], e2=xi[2]-yi[2];
      if(sqrtf(e0*e0+e1*e1+e2*e2)<0.1f) act=0;
    }
  }
  float e0=xi[0]-yi[0], e1=xi[1]-yi[1], e2=xi[2]-yi[2];
  out[NB+p]=act ? __expf(-(e0*e0+e1*e1+e2*e2))*__expf(-fun) : 0.f;
}

// ---- Phase 2: 4 rows per warp (amortize weight loads) ----
__global__ void __launch_bounds__(128) kmlp(){
  int tid=threadIdx.x, l=tid&31, wl=tid>>5;
  __shared__ __align__(16) float2 sh[4][4][HH];   // [warp][row][hidden]
  int gw=blockIdx.x*4+wl;
  int row=4*gw;
  int t=row>>13, p=row&(NB-1);

  // layer 1: inputs are uniform loads per row
  float4 bb=g_Pb[t*32+l];
  float4 acc[4];
  #pragma unroll
  for(int r=0;r<4;r++) acc[r]=bb;
  {
    const float4* Wp=g_P1+t*6*32;
    #pragma unroll
    for(int i=0;i<6;i++){
      float4 wv=Wp[i*32+l];
      #pragma unroll
      for(int r=0;r<4;r++){
        float x=g_in6[(t*6+i)*NB+p+r];
        acc[r].x+=x*wv.x; acc[r].y+=x*wv.y;
        acc[r].z+=x*wv.z; acc[r].w+=x*wv.w;
      }
    }
  }
  #pragma unroll
  for(int r=0;r<4;r++){
    ((float4*)sh[wl][r])[l]=make_float4(tanh_(acc[r].x),tanh_(acc[r].z),
                                        tanh_(acc[r].y),tanh_(acc[r].w));
  }
  __syncwarp();
  // layer 2
  float4 b2v=g_Pb2[t*32+l];
  #pragma unroll
  for(int r=0;r<4;r++) acc[r]=b2v;
  {
    const float4* Wp=g_P2+t*HH*32;
    #pragma unroll 8
    for(int i=0;i<HH;i++){
      float4 wv=Wp[i*32+l];
      #pragma unroll
      for(int r=0;r<4;r++){
        float2 x=sh[wl][r][i];
        acc[r].x+=x.x*wv.x; acc[r].y+=x.x*wv.y;
        acc[r].z+=x.y*wv.z; acc[r].w+=x.y*wv.w;
      }
    }
  }
  // layer 3: fold a6 before reduction; 4 scalars
  float s[4];
  #pragma unroll
  for(int r=0;r<4;r++){
    float2 h2=make_float2(tanh_(acc[r].x),tanh_(acc[r].y));
    float2 f2=make_float2(tanh_(acc[r].z),tanh_(acc[r].w));
    int idx=g_idx[t*NB+p+r];
    int ridx=idx>>8, rc=ridx*21+(idx&255);
    const float* Wp=g_W3+(t*NR+ridx)*6*HH;
    float sv=0.f;
    #pragma unroll
    for(int o=0;o<6;o++){
      float2 wa=*(const float2*)(Wp+o*HH+2*l);
      sv += g_a6[(t*6+o)*NB+p+r]*(h2.x*wa.x+h2.y*wa.y);
    }
    float2 aa2=*(const float2*)(g_A+(t*RC+rc)*HH+2*l);
    sv += f2.x*aa2.x+f2.y*aa2.y;
    s[r]=sv;
  }
  #pragma unroll
  for(int k=16;k;k>>=1){
    #pragma unroll
    for(int r=0;r<4;r++) s[r]+=__shfl_xor_sync(0xffffffffu,s[r],k);
  }
  if(l==0){
    float4 wt=*(const float4*)(g_wt+t*NB+p);
    float4 c0=*(const float4*)(g_c0+t*NB+p);
    float4 dd;
    dd.x=wt.x*(s[0]+c0.x); dd.y=wt.y*(s[1]+c0.y);
    dd.z=wt.z*(s[2]+c0.z); dd.w=wt.w*(s[3]+c0.w);
    *(float4*)(g_d+t*NB+p)=dd;
  }
}

// ---- Phase 3 ----
__global__ void __launch_bounds__(256) kfin(const float* __restrict__ u,
                                            float* __restrict__ out){
  int p=blockIdx.x*256+threadIdx.x;
  float acc=u[0];
  #pragma unroll 8
  for(int t=0;t<NS;t++) acc+=g_d[t*NB+p];
  out[p]=acc;
}

extern "C" void kernel_launch(void* const* d_in, const int* in_sizes, int n_in,
                              void* d_out, int out_size) {
  const float* u   =(const float*)d_in[0];
  const float* jr  =(const float*)d_in[1];
  const float* jl  =(const float*)d_in[2];
  const float* W1  =(const float*)d_in[3];
  const float* b1  =(const float*)d_in[4];
  const float* W2  =(const float*)d_in[5];
  const float* b2  =(const float*)d_in[6];
  const float* W3  =(const float*)d_in[7];
  const float* b3  =(const float*)d_in[8];
  const float* emb =(const float*)d_in[9];
  const float* Wf1 =(const float*)d_in[10];
  const float* bf1 =(const float*)d_in[11];
  const float* Wf2 =(const float*)d_in[12];
  const float* bf2 =(const float*)d_in[13];
  const float* Wf3 =(const float*)d_in[14];
  const float* bf3 =(const float*)d_in[15];
  const int*   rt0 =(const int*)  d_in[16];
  const float* xt0 =(const float*)d_in[17];
  const float* yt0 =(const float*)d_in[18];
  const float* dBx =(const float*)d_in[19];
  const float* dBy =(const float*)d_in[20];
  const float* juf =(const float*)d_in[21];
  const float* suf =(const float*)d_in[22];
  const float* mcu =(const float*)d_in[23];
  const float* jm  =(const float*)d_in[24];
  const float* cr  =(const float*)d_in[25];
  const float* cfr =(const float*)d_in[26];

  kh<<<NHB,256>>>(mcu,jm);
  kA2B<<<dim3(NS,8),256>>>(Wf3,bf3,jl,jr,cr);
  kEP<<<NS,384>>>(W3,emb,b3,W1,b1,W2,b2,Wf1,bf1,Wf2,bf2);
  ktraj<<<NB/64,64>>>(rt0,xt0,yt0,dBx,dBy,juf,suf,jm,cr,cfr,(float*)d_out);
  kmlp<<<NS*NB/16,128>>>();
  kfin<<<NB/256,256>>>(u,(float*)d_out);
}